// round 14
// baseline (speedup 1.0000x reference)
#include <cuda_runtime.h>
#include <cuda_fp16.h>
#include <math.h>
#include <stdint.h>

#define BB 64
#define NN 4096
#define DD 128
#define SS 65536
#define KTOP 16
#define NCH 8                         // filter chunks per b
#define CHSZ (SS / NCH)               // 8192 floats
#define NBLK 512                      // k4fh blocks (128 s each)
#define SCAP 2560                     // survivor capacity

typedef unsigned long long ull;

// ---------------- scratch (device globals; allocation-free) ----------------
__device__ float  g_qpart[BB * 4 * DD];   // per-CTA partial gelu sums
__device__ float  g_qn[BB * DD];          // normalized q: [b][d]
__device__ float  g_sim[(size_t)BB * SS]; // cosine sims fp32          (16 MB)
__device__ float  g_proto[BB * DD];
__device__ float  g_bmax[BB * NBLK];      // per-(b, block) max
__device__ int    g_scnt[BB];             // per-b survivor count
__device__ float  g_surv_v[BB * SCAP];
__device__ int    g_surv_i[BB * SCAP];

// ---------------- generic helpers ----------------
// fast exact-enough gelu: erf via Abramowitz-Stegun 7.1.26 (|eps|<=1.5e-7)
__device__ __forceinline__ float gelu_exact(float z) {
    float x = z * 0.70710678118654752f;
    float ax = fabsf(x);
    float t = __fdividef(1.0f, fmaf(0.3275911f, ax, 1.0f));
    float p = t * fmaf(t, fmaf(t, fmaf(t, fmaf(t, 1.061405429f, -1.453152027f),
                                       1.421413741f), -0.284496736f), 0.254829592f);
    float e = __expf(-x * x);
    float er = copysignf(fmaf(-p, e, 1.0f), x);
    return 0.5f * z * (1.0f + er);
}
// pack two fp32 -> f16x2 (lo = first arg in low half)
__device__ __forceinline__ uint32_t hpack(float lo, float hi) {
    uint32_t r;
    asm("cvt.rn.f16x2.f32 %0, %1, %2;" : "=r"(r) : "f"(hi), "f"(lo));
    return r;
}
// split float4 -> fp16 hi pair + fp16 lo pair (hi+lo ~ 2^-22 of v)
__device__ __forceinline__ void hsplit4(float4 v, uint2& h, uint2& l) {
    __half hx = __float2half_rn(v.x), hy = __float2half_rn(v.y);
    __half hz = __float2half_rn(v.z), hw = __float2half_rn(v.w);
    h = make_uint2(((uint32_t)__half_as_ushort(hy) << 16) | __half_as_ushort(hx),
                   ((uint32_t)__half_as_ushort(hw) << 16) | __half_as_ushort(hz));
    l = make_uint2(hpack(v.x - __half2float(hx), v.y - __half2float(hy)),
                   hpack(v.z - __half2float(hz), v.w - __half2float(hw)));
}

// fp16 m16n8k16 mma.sync
__device__ __forceinline__ void mma_f16(float* c, uint32_t a0, uint32_t a1,
                                        uint32_t a2, uint32_t a3,
                                        uint32_t b0, uint32_t b1) {
    asm volatile(
        "mma.sync.aligned.m16n8k16.row.col.f32.f16.f16.f32 "
        "{%0,%1,%2,%3}, {%4,%5,%6,%7}, {%8,%9}, {%0,%1,%2,%3};"
        : "+f"(c[0]), "+f"(c[1]), "+f"(c[2]), "+f"(c[3])
        : "r"(a0), "r"(a1), "r"(a2), "r"(a3), "r"(b0), "r"(b1));
}

// ---------------- K2: fp16 mma conv1d+GeLU+sum-over-n -------------------
// grid 256 = (b, quarter-n), 128 threads (4 warps = 4 e-quarters),
// tile 64n x 128e, 32 steps, 2-stage A ring, 2 CTAs/SM.
#define WS16 136                     // f16 per W row (128 + 8 pad)
#define AS16 72                      // f16 per A row (64 + 8 pad)
#define AB16 (64 * AS16)             // 4608 f16 per A buffer (9216 B)
#define O_W    0                     // 34816 B
#define O_A    34816                 // 2 * 9216 = 18432 B
#define O_BIAS 53248                 // 512 B
#define O_RED  53760                 // 512 B
#define K2_SMEM 54784

__global__ void __launch_bounds__(128, 2) k2_mma(const float* __restrict__ x,
                                                 const float* __restrict__ w,
                                                 const float* __restrict__ bias) {
    extern __shared__ char smc[];
    uint16_t* ws    = (uint16_t*)(smc + O_W);
    uint16_t* ab    = (uint16_t*)(smc + O_A);
    float*    sbias = (float*)(smc + O_BIAS);
    float*    red   = (float*)(smc + O_RED);

    int tid = threadIdx.x, wid = tid >> 5, lane = tid & 31;
    int g = lane >> 2, kc = lane & 3;
    int cta = blockIdx.x, b = cta >> 2, quarter = cta & 3;
    const float* xb = x + ((size_t)b * NN + (size_t)quarter * 1024) * DD;

    for (int i = tid; i < 4096; i += 128) {      // float4 over [128e][32]
        float4 v = ((const float4*)w)[i];
        int e = i >> 5, d0 = (i & 31) * 4;
        *(uint2*)&ws[e * WS16 + d0] = make_uint2(hpack(v.x, v.y), hpack(v.z, v.w));
    }
    sbias[tid] = bias[tid];

    int ew = wid * 32;

    float c[4][4][4];
    #pragma unroll
    for (int mf = 0; mf < 4; ++mf)
        #pragma unroll
        for (int ef = 0; ef < 4; ++ef)
            #pragma unroll
            for (int q = 0; q < 4; ++q) c[mf][ef][q] = 0.f;
    float es[8];
    #pragma unroll
    for (int s = 0; s < 8; ++s) es[s] = 0.f;

    float4 r8[8];
    auto ldg = [&](int gstep) {
        int t = gstep >> 1, h = gstep & 1;
        const float* base = xb + (size_t)t * (64 * DD) + h * 64;
        #pragma unroll
        for (int j = 0; j < 8; ++j) {
            int idx = j * 128 + tid;
            int row = idx >> 4, seg = idx & 15;
            r8[j] = *(const float4*)(base + (size_t)row * DD + seg * 4);
        }
    };
    auto sts = [&](int buf) {
        uint16_t* d = ab + buf * AB16;
        #pragma unroll
        for (int j = 0; j < 8; ++j) {
            int idx = j * 128 + tid;
            int row = idx >> 4, seg = idx & 15;
            *(uint2*)&d[row * AS16 + seg * 4] =
                make_uint2(hpack(r8[j].x, r8[j].y), hpack(r8[j].z, r8[j].w));
        }
    };

    ldg(0); sts(0);
    ldg(1);
    __syncthreads();

    float bs[8];
    #pragma unroll
    for (int ef = 0; ef < 4; ++ef) {
        bs[ef * 2 + 0] = sbias[ew + ef * 8 + 2 * kc + 0];
        bs[ef * 2 + 1] = sbias[ew + ef * 8 + 2 * kc + 1];
    }

    #pragma unroll 1
    for (int step = 0; step < 32; ++step) {
        if (step < 31) sts((step + 1) & 1);
        if (step < 30) ldg(step + 2);

        const uint16_t* A = ab + (step & 1) * AB16;
        int kg0 = (step & 1) * 64;
        #pragma unroll
        for (int ks = 0; ks < 4; ++ks) {
            int kb = ks * 16;
            uint32_t a[4][4];
            #pragma unroll
            for (int mf = 0; mf < 4; ++mf) {
                int r = g + mf * 16;
                a[mf][0] = *(const uint32_t*)&A[r * AS16 + kb + 2 * kc];
                a[mf][1] = *(const uint32_t*)&A[(r + 8) * AS16 + kb + 2 * kc];
                a[mf][2] = *(const uint32_t*)&A[r * AS16 + kb + 2 * kc + 8];
                a[mf][3] = *(const uint32_t*)&A[(r + 8) * AS16 + kb + 2 * kc + 8];
            }
            #pragma unroll
            for (int ef = 0; ef < 4; ++ef) {
                int e = ew + ef * 8 + g;
                uint32_t b0 = *(const uint32_t*)&ws[e * WS16 + kg0 + kb + 2 * kc];
                uint32_t b1 = *(const uint32_t*)&ws[e * WS16 + kg0 + kb + 2 * kc + 8];
                #pragma unroll
                for (int mf = 0; mf < 4; ++mf)
                    mma_f16(c[mf][ef], a[mf][0], a[mf][1], a[mf][2], a[mf][3], b0, b1);
            }
        }

        if ((step & 1) == 1) {
            #pragma unroll
            for (int mf = 0; mf < 4; ++mf)
                #pragma unroll
                for (int ef = 0; ef < 4; ++ef)
                    #pragma unroll
                    for (int q = 0; q < 4; ++q) {
                        int s = ef * 2 + (q & 1);
                        es[s] += gelu_exact(c[mf][ef][q] + bs[s]);
                        c[mf][ef][q] = 0.f;
                    }
        }
        __syncthreads();
    }

    #pragma unroll
    for (int off = 16; off >= 4; off >>= 1)
        #pragma unroll
        for (int s = 0; s < 8; ++s)
            es[s] += __shfl_xor_sync(0xffffffffu, es[s], off);
    if (g == 0) {
        #pragma unroll
        for (int s = 0; s < 8; ++s) {
            int ecol = ew + (s >> 1) * 8 + 2 * kc + (s & 1);
            red[ecol] = es[s];
        }
    }
    __syncthreads();
    g_qpart[(b * 4 + quarter) * 128 + tid] = red[tid];
}

// ---------------- K3: finalize q + normalize ([b][d] layout) ------------
__global__ void k3_q() {
    int b = blockIdx.x, e = threadIdx.x;
    float q = g_qpart[b * 512 + e] + g_qpart[b * 512 + 128 + e] +
              g_qpart[b * 512 + 256 + e] + g_qpart[b * 512 + 384 + e];
    __shared__ float sr[128];
    sr[e] = q * q;
    __syncthreads();
    for (int off = 64; off; off >>= 1) {
        if (e < off) sr[e] += sr[e + off];
        __syncthreads();
    }
    float inv = 1.0f / fmaxf(sqrtf(sr[0]), 1e-12f);
    g_qn[b * 128 + e] = q * inv;
}

// ---------------- K4fh: precision-split fp16 MMA sim GEMM ---------------
// Block = 128 s x 64 b. qn, mn each split hi+lo fp16; 3 accumulating
// passes (qh*mh + qh*ml + ql*mh) -> sim error ~1e-6; fp32 sim storage.
#define QS16 136                     // f16 per row (128 + 8 pad)
#define H_QNH  0                     // 17408 B
#define H_QNL  17408                 // 17408 B
#define H_MNH  34816                 // 34816 B
#define H_MNL  69632                 // 34816 B
#define H_WMAX 104448                // 2048 B
#define K4_SMEM 106496

__global__ void __launch_bounds__(256, 2) k4fh(const float* __restrict__ mem) {
    extern __shared__ char sm4[];
    uint16_t* qh = (uint16_t*)(sm4 + H_QNH);
    uint16_t* ql = (uint16_t*)(sm4 + H_QNL);
    uint16_t* mh = (uint16_t*)(sm4 + H_MNH);
    uint16_t* ml = (uint16_t*)(sm4 + H_MNL);
    float*  wmax = (float*)(sm4 + H_WMAX);
    int tid = threadIdx.x, wid = tid >> 5, lane = tid & 31;
    int g = lane >> 2, kc = lane & 3;
    int s0 = blockIdx.x * 128;

    if (blockIdx.x == 0 && tid < BB) g_scnt[tid] = 0;   // reset for k5s

    // ---- stage qn hi/lo as fp16 [b][k] ----
    #pragma unroll
    for (int j = 0; j < 8; ++j) {
        int idx = j * 256 + tid;                 // float4 over [64][128]
        int brow = idx >> 5, seg = idx & 31;
        float4 v = ((const float4*)g_qn)[idx];
        uint2 h2, l2;
        hsplit4(v, h2, l2);
        *(uint2*)&qh[brow * QS16 + seg * 4] = h2;
        *(uint2*)&ql[brow * QS16 + seg * 4] = l2;
    }

    // ---- normalize memory rows -> fp16 hi/lo [s][k] (native layout) ----
    {
        int row = tid >> 1, h = tid & 1;
        const float4* src = (const float4*)(mem + (size_t)(s0 + row) * 128 + h * 64);
        float acc = 0.f;
        #pragma unroll
        for (int i = 0; i < 16; ++i) {
            float4 v = src[i];
            acc = fmaf(v.x, v.x, acc); acc = fmaf(v.y, v.y, acc);
            acc = fmaf(v.z, v.z, acc); acc = fmaf(v.w, v.w, acc);
        }
        acc += __shfl_xor_sync(0xffffffffu, acc, 1);
        float inv = 1.0f / fmaxf(sqrtf(acc), 1e-12f);
        uint16_t* dh = mh + row * QS16 + h * 64;
        uint16_t* dl = ml + row * QS16 + h * 64;
        #pragma unroll
        for (int i = 0; i < 16; ++i) {
            float4 v = src[i];                   // L1 hit (just read)
            float4 n = make_float4(v.x * inv, v.y * inv, v.z * inv, v.w * inv);
            uint2 h2, l2;
            hsplit4(n, h2, l2);
            *(uint2*)(dh + i * 4) = h2;
            *(uint2*)(dl + i * 4) = l2;
        }
    }
    __syncthreads();

    // ---- GEMM: D[64b][16s-slice] per warp, k=128, 3 precision passes ----
    int sw = wid * 16;
    float c[4][2][4];
    #pragma unroll
    for (int mf = 0; mf < 4; ++mf)
        #pragma unroll
        for (int ef = 0; ef < 2; ++ef)
            #pragma unroll
            for (int q = 0; q < 4; ++q) c[mf][ef][q] = 0.f;

    #pragma unroll
    for (int ks = 0; ks < 8; ++ks) {
        int kb = ks * 16;
        uint32_t ah[4][4], al[4][4];
        #pragma unroll
        for (int mf = 0; mf < 4; ++mf) {
            int r = g + mf * 16;
            ah[mf][0] = *(const uint32_t*)&qh[r * QS16 + kb + 2 * kc];
            ah[mf][1] = *(const uint32_t*)&qh[(r + 8) * QS16 + kb + 2 * kc];
            ah[mf][2] = *(const uint32_t*)&qh[r * QS16 + kb + 2 * kc + 8];
            ah[mf][3] = *(const uint32_t*)&qh[(r + 8) * QS16 + kb + 2 * kc + 8];
            al[mf][0] = *(const uint32_t*)&ql[r * QS16 + kb + 2 * kc];
            al[mf][1] = *(const uint32_t*)&ql[(r + 8) * QS16 + kb + 2 * kc];
            al[mf][2] = *(const uint32_t*)&ql[r * QS16 + kb + 2 * kc + 8];
            al[mf][3] = *(const uint32_t*)&ql[(r + 8) * QS16 + kb + 2 * kc + 8];
        }
        #pragma unroll
        for (int ef = 0; ef < 2; ++ef) {
            int n = sw + ef * 8 + g;
            uint32_t bh0 = *(const uint32_t*)&mh[n * QS16 + kb + 2 * kc];
            uint32_t bh1 = *(const uint32_t*)&mh[n * QS16 + kb + 2 * kc + 8];
            uint32_t bl0 = *(const uint32_t*)&ml[n * QS16 + kb + 2 * kc];
            uint32_t bl1 = *(const uint32_t*)&ml[n * QS16 + kb + 2 * kc + 8];
            #pragma unroll
            for (int mf = 0; mf < 4; ++mf) {
                mma_f16(c[mf][ef], ah[mf][0], ah[mf][1], ah[mf][2], ah[mf][3], bh0, bh1);
                mma_f16(c[mf][ef], ah[mf][0], ah[mf][1], ah[mf][2], ah[mf][3], bl0, bl1);
                mma_f16(c[mf][ef], al[mf][0], al[mf][1], al[mf][2], al[mf][3], bh0, bh1);
            }
        }
    }

    // ---- epilogue: store fp32 sims + per-b row maxes ----
    #pragma unroll
    for (int mf = 0; mf < 4; ++mf) {
        #pragma unroll
        for (int h = 0; h < 2; ++h) {
            int row = mf * 16 + 8 * h + g;       // b index
            float rm = -1e30f;
            #pragma unroll
            for (int ef = 0; ef < 2; ++ef) {
                float lo = c[mf][ef][2 * h], hi = c[mf][ef][2 * h + 1];
                *(float2*)&g_sim[(size_t)row * SS + s0 + sw + ef * 8 + 2 * kc] =
                    make_float2(lo, hi);
                rm = fmaxf(rm, fmaxf(lo, hi));
            }
            rm = fmaxf(rm, __shfl_xor_sync(0xffffffffu, rm, 1));
            rm = fmaxf(rm, __shfl_xor_sync(0xffffffffu, rm, 2));
            if (kc == 0) wmax[wid * 64 + row] = rm;
        }
    }
    __syncthreads();
    if (tid < 64) {
        float m = wmax[tid];
        #pragma unroll
        for (int w = 1; w < 8; ++w) m = fmaxf(m, wmax[w * 64 + tid]);
        g_bmax[tid * NBLK + blockIdx.x] = m;
    }
}

// ---------------- K5s: inline threshold + fp32 stream filter ------------
// T = min over 32 group-maxes (16 bmax each): provably <= v16.
__global__ void __launch_bounds__(256) k5s() {
    __shared__ float sT;
    int b = blockIdx.y, ch = blockIdx.x;
    int tid = threadIdx.x, lane = tid & 31;

    if (tid < 32) {
        float mx = -1e30f;
        #pragma unroll
        for (int j = 0; j < NBLK / 32; ++j)
            mx = fmaxf(mx, g_bmax[b * NBLK + lane * (NBLK / 32) + j]);
        #pragma unroll
        for (int off = 16; off; off >>= 1)
            mx = fminf(mx, __shfl_xor_sync(0xffffffffu, mx, off));
        if (lane == 0) sT = mx;
    }
    __syncthreads();

    float T = sT;
    const float4* rowv = (const float4*)(g_sim + (size_t)b * SS + (size_t)ch * CHSZ);
    int base = ch * CHSZ;
    #pragma unroll
    for (int it = 0; it < 8; ++it) {
        float4 v = rowv[it * 256 + tid];
        float vm = fmaxf(fmaxf(v.x, v.y), fmaxf(v.z, v.w));
        if (vm >= T) {
            float vals[4] = {v.x, v.y, v.z, v.w};
            int sb = base + (it * 256 + tid) * 4;
            #pragma unroll
            for (int j = 0; j < 4; ++j) {
                if (vals[j] >= T) {
                    int p = atomicAdd(&g_scnt[b], 1);
                    if (p < SCAP) {
                        g_surv_v[b * SCAP + p] = vals[j];
                        g_surv_i[b * SCAP + p] = sb + j;
                    }
                }
            }
        }
    }
}

// ---------------- K5b: final top-16 + softmax + proto gather ------------
__global__ void __launch_bounds__(128) k5b(const float* __restrict__ mem) {
    __shared__ float cv[SCAP];
    __shared__ int   ci[SCAP];
    __shared__ float selv[KTOP];
    __shared__ int   seli[KTOP];
    __shared__ float attn[KTOP];
    int b = blockIdx.x, tid = threadIdx.x, lane = tid & 31;
    int n = min(g_scnt[b], SCAP);

    for (int i = tid; i < n; i += 128) {
        cv[i] = g_surv_v[b * SCAP + i];
        ci[i] = g_surv_i[b * SCAP + i];
    }
    __syncthreads();

    if (tid < 32) {
        #pragma unroll 1
        for (int r = 0; r < KTOP; ++r) {
            float mv = -1e30f; int gi = 0x7fffffff; int mi = 0;
            for (int i = lane; i < n; i += 32) {
                float v = cv[i]; int idx = ci[i];
                if (v > mv || (v == mv && idx < gi)) { mv = v; gi = idx; mi = i; }
            }
            float bv = mv; int bgi = gi; int bmi = mi;
            #pragma unroll
            for (int off = 16; off; off >>= 1) {
                float ov  = __shfl_xor_sync(0xffffffffu, bv, off);
                int   ogi = __shfl_xor_sync(0xffffffffu, bgi, off);
                int   omi = __shfl_xor_sync(0xffffffffu, bmi, off);
                if (ov > bv || (ov == bv && ogi < bgi)) { bv = ov; bgi = ogi; bmi = omi; }
            }
            if (lane == 0) {
                selv[r] = bv; seli[r] = bgi;
                cv[bmi] = -1e30f;
            }
            __syncwarp();
        }
        if (lane == 0) {
            float mx = selv[0];
            float e[KTOP], ssum = 0.f;
            #pragma unroll
            for (int k = 0; k < KTOP; ++k) { e[k] = expf(selv[k] - mx); ssum += e[k]; }
            #pragma unroll
            for (int k = 0; k < KTOP; ++k) attn[k] = e[k] / ssum;
        }
    }
    __syncthreads();

    float acc = 0.f;
    #pragma unroll
    for (int k = 0; k < KTOP; ++k)
        acc = fmaf(attn[k], mem[(size_t)seli[k] * 128 + tid], acc);
    g_proto[b * 128 + tid] = acc;
}

// ---------------- K6: out = x + scale * proto ---------------------------
__global__ void __launch_bounds__(256) k6_add(const float* __restrict__ x,
                                              const float* __restrict__ scale_p,
                                              float* __restrict__ out) {
    __shared__ float pr[128];
    __shared__ float sc;
    int b = blockIdx.y;
    if (threadIdx.x < 128) pr[threadIdx.x] = g_proto[b * 128 + threadIdx.x];
    if (threadIdx.x == 0) sc = *scale_p;
    __syncthreads();

    float s = sc;
    const float4* xv = (const float4*)x;
    float4* ov = (float4*)out;
    size_t f0 = ((size_t)b * (NN * DD) + (size_t)blockIdx.x * 4096) >> 2;
    #pragma unroll
    for (int it = 0; it < 4; ++it) {
        size_t f = f0 + it * 256 + threadIdx.x;
        float4 v = xv[f];
        int d4 = (int)(f & 31);
        const float* p = &pr[d4 * 4];
        v.x = fmaf(s, p[0], v.x);
        v.y = fmaf(s, p[1], v.y);
        v.z = fmaf(s, p[2], v.z);
        v.w = fmaf(s, p[3], v.w);
        ov[f] = v;
    }
}

// ---------------- launch -------------------------------------------------
extern "C" void kernel_launch(void* const* d_in, const int* in_sizes, int n_in,
                              void* d_out, int out_size) {
    const float* x      = (const float*)d_in[0];
    const float* conv_w = (const float*)d_in[1];
    const float* conv_b = (const float*)d_in[2];
    const float* memory = (const float*)d_in[3];
    const float* scale  = (const float*)d_in[4];
    float* out = (float*)d_out;

    cudaFuncSetAttribute(k2_mma, cudaFuncAttributeMaxDynamicSharedMemorySize, K2_SMEM);
    cudaFuncSetAttribute(k4fh, cudaFuncAttributeMaxDynamicSharedMemorySize, K4_SMEM);

    k2_mma<<<BB * 4, 128, K2_SMEM>>>(x, conv_w, conv_b);
    k3_q<<<BB, 128>>>();
    k4fh<<<NBLK, 256, K4_SMEM>>>(memory);
    dim3 g5s(NCH, BB);
    k5s<<<g5s, 256>>>();
    k5b<<<BB, 128>>>(memory);
    dim3 g6(128, BB);
    k6_add<<<g6, 256>>>(x, scale, out);
    (void)in_sizes; (void)n_in; (void)out_size;
}

// round 15
// speedup vs baseline: 1.0273x; 1.0273x over previous
#include <cuda_runtime.h>
#include <cuda_fp16.h>
#include <math.h>
#include <stdint.h>

#define BB 64
#define NN 4096
#define DD 128
#define SS 65536
#define KTOP 16
#define NCH 8                         // filter chunks per b
#define CHSZ (SS / NCH)               // 8192 floats
#define NBLK 512                      // k4fh blocks (128 s each)
#define SCAP 2560                     // survivor capacity

typedef unsigned long long ull;

// ---------------- scratch (device globals; allocation-free) ----------------
__device__ float  g_qpart[BB * 4 * DD];   // per-CTA partial gelu sums
__device__ float  g_qn[BB * DD];          // normalized q: [b][d]
__device__ float  g_sim[(size_t)BB * SS]; // cosine sims fp32          (16 MB)
__device__ float  g_proto[BB * DD];
__device__ float  g_bmax[BB * NBLK];      // per-(b, block) max
__device__ int    g_scnt[BB];             // per-b survivor count
__device__ float  g_surv_v[BB * SCAP];
__device__ int    g_surv_i[BB * SCAP];

// ---------------- generic helpers ----------------
// gelu via A&S 7.1.28 erf (|eps|<=3e-7), single MUFU (rcp.approx)
__device__ __forceinline__ float gelu_exact(float z) {
    float x = z * 0.70710678118654752f;
    float ax = fabsf(x);
    float p = fmaf(ax, 0.0000430638f, 0.0002765672f);
    p = fmaf(ax, p, 0.0001520143f);
    p = fmaf(ax, p, 0.0092705272f);
    p = fmaf(ax, p, 0.0422820123f);
    p = fmaf(ax, p, 0.0705230784f);
    p = fmaf(ax, p, 1.0f);
    float r;
    asm("rcp.approx.f32 %0, %1;" : "=f"(r) : "f"(p));
    float r2 = r * r;
    float r4 = r2 * r2;
    float r8 = r4 * r4;
    float r16 = r8 * r8;
    float er = copysignf(1.0f - r16, x);
    return 0.5f * z * (1.0f + er);
}
// pack two fp32 -> f16x2 (lo = first arg in low half)
__device__ __forceinline__ uint32_t hpack(float lo, float hi) {
    uint32_t r;
    asm("cvt.rn.f16x2.f32 %0, %1, %2;" : "=r"(r) : "f"(hi), "f"(lo));
    return r;
}
// split float4 -> fp16 hi pair + fp16 lo pair (hi+lo ~ 2^-22 of v)
__device__ __forceinline__ void hsplit4(float4 v, uint2& h, uint2& l) {
    __half hx = __float2half_rn(v.x), hy = __float2half_rn(v.y);
    __half hz = __float2half_rn(v.z), hw = __float2half_rn(v.w);
    h = make_uint2(((uint32_t)__half_as_ushort(hy) << 16) | __half_as_ushort(hx),
                   ((uint32_t)__half_as_ushort(hw) << 16) | __half_as_ushort(hz));
    l = make_uint2(hpack(v.x - __half2float(hx), v.y - __half2float(hy)),
                   hpack(v.z - __half2float(hz), v.w - __half2float(hw)));
}

// fp16 m16n8k16 mma.sync
__device__ __forceinline__ void mma_f16(float* c, uint32_t a0, uint32_t a1,
                                        uint32_t a2, uint32_t a3,
                                        uint32_t b0, uint32_t b1) {
    asm volatile(
        "mma.sync.aligned.m16n8k16.row.col.f32.f16.f16.f32 "
        "{%0,%1,%2,%3}, {%4,%5,%6,%7}, {%8,%9}, {%0,%1,%2,%3};"
        : "+f"(c[0]), "+f"(c[1]), "+f"(c[2]), "+f"(c[3])
        : "r"(a0), "r"(a1), "r"(a2), "r"(a3), "r"(b0), "r"(b1));
}

// ---------------- K2: fp16 mma conv1d+GeLU+sum-over-n -------------------
// grid 256 = (b, quarter-n), 128 threads (4 warps = 4 e-quarters),
// tile 64n x 128e, 32 steps, 2-stage A ring, 2 CTAs/SM.
#define WS16 136                     // f16 per W row (128 + 8 pad)
#define AS16 72                      // f16 per A row (64 + 8 pad)
#define AB16 (64 * AS16)             // 4608 f16 per A buffer (9216 B)
#define O_W    0                     // 34816 B
#define O_A    34816                 // 2 * 9216 = 18432 B
#define O_BIAS 53248                 // 512 B
#define O_RED  53760                 // 512 B
#define K2_SMEM 54784

__global__ void __launch_bounds__(128, 2) k2_mma(const float* __restrict__ x,
                                                 const float* __restrict__ w,
                                                 const float* __restrict__ bias) {
    extern __shared__ char smc[];
    uint16_t* ws    = (uint16_t*)(smc + O_W);
    uint16_t* ab    = (uint16_t*)(smc + O_A);
    float*    sbias = (float*)(smc + O_BIAS);
    float*    red   = (float*)(smc + O_RED);

    int tid = threadIdx.x, wid = tid >> 5, lane = tid & 31;
    int g = lane >> 2, kc = lane & 3;
    int cta = blockIdx.x, b = cta >> 2, quarter = cta & 3;
    const float* xb = x + ((size_t)b * NN + (size_t)quarter * 1024) * DD;

    for (int i = tid; i < 4096; i += 128) {      // float4 over [128e][32]
        float4 v = ((const float4*)w)[i];
        int e = i >> 5, d0 = (i & 31) * 4;
        *(uint2*)&ws[e * WS16 + d0] = make_uint2(hpack(v.x, v.y), hpack(v.z, v.w));
    }
    sbias[tid] = bias[tid];

    int ew = wid * 32;

    float c[4][4][4];
    #pragma unroll
    for (int mf = 0; mf < 4; ++mf)
        #pragma unroll
        for (int ef = 0; ef < 4; ++ef)
            #pragma unroll
            for (int q = 0; q < 4; ++q) c[mf][ef][q] = 0.f;
    float es[8];
    #pragma unroll
    for (int s = 0; s < 8; ++s) es[s] = 0.f;

    float4 r8[8];
    auto ldg = [&](int gstep) {
        int t = gstep >> 1, h = gstep & 1;
        const float* base = xb + (size_t)t * (64 * DD) + h * 64;
        #pragma unroll
        for (int j = 0; j < 8; ++j) {
            int idx = j * 128 + tid;
            int row = idx >> 4, seg = idx & 15;
            r8[j] = *(const float4*)(base + (size_t)row * DD + seg * 4);
        }
    };
    auto sts = [&](int buf) {
        uint16_t* d = ab + buf * AB16;
        #pragma unroll
        for (int j = 0; j < 8; ++j) {
            int idx = j * 128 + tid;
            int row = idx >> 4, seg = idx & 15;
            *(uint2*)&d[row * AS16 + seg * 4] =
                make_uint2(hpack(r8[j].x, r8[j].y), hpack(r8[j].z, r8[j].w));
        }
    };

    ldg(0); sts(0);
    ldg(1);
    __syncthreads();

    float bs[8];
    #pragma unroll
    for (int ef = 0; ef < 4; ++ef) {
        bs[ef * 2 + 0] = sbias[ew + ef * 8 + 2 * kc + 0];
        bs[ef * 2 + 1] = sbias[ew + ef * 8 + 2 * kc + 1];
    }

    #pragma unroll 1
    for (int step = 0; step < 32; ++step) {
        if (step < 31) sts((step + 1) & 1);
        if (step < 30) ldg(step + 2);

        const uint16_t* A = ab + (step & 1) * AB16;
        int kg0 = (step & 1) * 64;
        #pragma unroll
        for (int ks = 0; ks < 4; ++ks) {
            int kb = ks * 16;
            uint32_t a[4][4];
            #pragma unroll
            for (int mf = 0; mf < 4; ++mf) {
                int r = g + mf * 16;
                a[mf][0] = *(const uint32_t*)&A[r * AS16 + kb + 2 * kc];
                a[mf][1] = *(const uint32_t*)&A[(r + 8) * AS16 + kb + 2 * kc];
                a[mf][2] = *(const uint32_t*)&A[r * AS16 + kb + 2 * kc + 8];
                a[mf][3] = *(const uint32_t*)&A[(r + 8) * AS16 + kb + 2 * kc + 8];
            }
            #pragma unroll
            for (int ef = 0; ef < 4; ++ef) {
                int e = ew + ef * 8 + g;
                uint32_t b0 = *(const uint32_t*)&ws[e * WS16 + kg0 + kb + 2 * kc];
                uint32_t b1 = *(const uint32_t*)&ws[e * WS16 + kg0 + kb + 2 * kc + 8];
                #pragma unroll
                for (int mf = 0; mf < 4; ++mf)
                    mma_f16(c[mf][ef], a[mf][0], a[mf][1], a[mf][2], a[mf][3], b0, b1);
            }
        }

        if ((step & 1) == 1) {
            #pragma unroll
            for (int mf = 0; mf < 4; ++mf)
                #pragma unroll
                for (int ef = 0; ef < 4; ++ef)
                    #pragma unroll
                    for (int q = 0; q < 4; ++q) {
                        int s = ef * 2 + (q & 1);
                        es[s] += gelu_exact(c[mf][ef][q] + bs[s]);
                        c[mf][ef][q] = 0.f;
                    }
        }
        __syncthreads();
    }

    #pragma unroll
    for (int off = 16; off >= 4; off >>= 1)
        #pragma unroll
        for (int s = 0; s < 8; ++s)
            es[s] += __shfl_xor_sync(0xffffffffu, es[s], off);
    if (g == 0) {
        #pragma unroll
        for (int s = 0; s < 8; ++s) {
            int ecol = ew + (s >> 1) * 8 + 2 * kc + (s & 1);
            red[ecol] = es[s];
        }
    }
    __syncthreads();
    g_qpart[(b * 4 + quarter) * 128 + tid] = red[tid];
}

// ---------------- K3: finalize q + normalize ([b][d] layout) ------------
__global__ void k3_q() {
    int b = blockIdx.x, e = threadIdx.x;
    float q = g_qpart[b * 512 + e] + g_qpart[b * 512 + 128 + e] +
              g_qpart[b * 512 + 256 + e] + g_qpart[b * 512 + 384 + e];
    __shared__ float sr[128];
    sr[e] = q * q;
    __syncthreads();
    for (int off = 64; off; off >>= 1) {
        if (e < off) sr[e] += sr[e + off];
        __syncthreads();
    }
    float inv = 1.0f / fmaxf(sqrtf(sr[0]), 1e-12f);
    g_qn[b * 128 + e] = q * inv;
}

// ---------------- K4fh: precision-split fp16 MMA sim GEMM ---------------
// Block = 128 s x 64 b. qn, mn each split hi+lo fp16; 3 accumulating
// passes (qh*mh + qh*ml + ql*mh) -> sim error ~1e-6; fp32 sim storage.
#define QS16 136                     // f16 per row (128 + 8 pad)
#define H_QNH  0                     // 17408 B
#define H_QNL  17408                 // 17408 B
#define H_MNH  34816                 // 34816 B
#define H_MNL  69632                 // 34816 B
#define H_WMAX 104448                // 2048 B
#define K4_SMEM 106496

__global__ void __launch_bounds__(256, 2) k4fh(const float* __restrict__ mem) {
    extern __shared__ char sm4[];
    uint16_t* qh = (uint16_t*)(sm4 + H_QNH);
    uint16_t* ql = (uint16_t*)(sm4 + H_QNL);
    uint16_t* mh = (uint16_t*)(sm4 + H_MNH);
    uint16_t* ml = (uint16_t*)(sm4 + H_MNL);
    float*  wmax = (float*)(sm4 + H_WMAX);
    int tid = threadIdx.x, wid = tid >> 5, lane = tid & 31;
    int g = lane >> 2, kc = lane & 3;
    int s0 = blockIdx.x * 128;

    if (blockIdx.x == 0 && tid < BB) g_scnt[tid] = 0;   // reset for k5s

    // ---- stage qn hi/lo as fp16 [b][k] ----
    #pragma unroll
    for (int j = 0; j < 8; ++j) {
        int idx = j * 256 + tid;                 // float4 over [64][128]
        int brow = idx >> 5, seg = idx & 31;
        float4 v = ((const float4*)g_qn)[idx];
        uint2 h2, l2;
        hsplit4(v, h2, l2);
        *(uint2*)&qh[brow * QS16 + seg * 4] = h2;
        *(uint2*)&ql[brow * QS16 + seg * 4] = l2;
    }

    // ---- normalize memory rows -> fp16 hi/lo [s][k] (native layout) ----
    {
        int row = tid >> 1, h = tid & 1;
        const float4* src = (const float4*)(mem + (size_t)(s0 + row) * 128 + h * 64);
        float acc = 0.f;
        #pragma unroll
        for (int i = 0; i < 16; ++i) {
            float4 v = src[i];
            acc = fmaf(v.x, v.x, acc); acc = fmaf(v.y, v.y, acc);
            acc = fmaf(v.z, v.z, acc); acc = fmaf(v.w, v.w, acc);
        }
        acc += __shfl_xor_sync(0xffffffffu, acc, 1);
        float inv = 1.0f / fmaxf(sqrtf(acc), 1e-12f);
        uint16_t* dh = mh + row * QS16 + h * 64;
        uint16_t* dl = ml + row * QS16 + h * 64;
        #pragma unroll
        for (int i = 0; i < 16; ++i) {
            float4 v = src[i];                   // L1 hit (just read)
            float4 n = make_float4(v.x * inv, v.y * inv, v.z * inv, v.w * inv);
            uint2 h2, l2;
            hsplit4(n, h2, l2);
            *(uint2*)(dh + i * 4) = h2;
            *(uint2*)(dl + i * 4) = l2;
        }
    }
    __syncthreads();

    // ---- GEMM: D[64b][16s-slice] per warp, k=128, 3 precision passes ----
    int sw = wid * 16;
    float c[4][2][4];
    #pragma unroll
    for (int mf = 0; mf < 4; ++mf)
        #pragma unroll
        for (int ef = 0; ef < 2; ++ef)
            #pragma unroll
            for (int q = 0; q < 4; ++q) c[mf][ef][q] = 0.f;

    #pragma unroll
    for (int ks = 0; ks < 8; ++ks) {
        int kb = ks * 16;
        uint32_t ah[4][4], al[4][4];
        #pragma unroll
        for (int mf = 0; mf < 4; ++mf) {
            int r = g + mf * 16;
            ah[mf][0] = *(const uint32_t*)&qh[r * QS16 + kb + 2 * kc];
            ah[mf][1] = *(const uint32_t*)&qh[(r + 8) * QS16 + kb + 2 * kc];
            ah[mf][2] = *(const uint32_t*)&qh[r * QS16 + kb + 2 * kc + 8];
            ah[mf][3] = *(const uint32_t*)&qh[(r + 8) * QS16 + kb + 2 * kc + 8];
            al[mf][0] = *(const uint32_t*)&ql[r * QS16 + kb + 2 * kc];
            al[mf][1] = *(const uint32_t*)&ql[(r + 8) * QS16 + kb + 2 * kc];
            al[mf][2] = *(const uint32_t*)&ql[r * QS16 + kb + 2 * kc + 8];
            al[mf][3] = *(const uint32_t*)&ql[(r + 8) * QS16 + kb + 2 * kc + 8];
        }
        #pragma unroll
        for (int ef = 0; ef < 2; ++ef) {
            int n = sw + ef * 8 + g;
            uint32_t bh0 = *(const uint32_t*)&mh[n * QS16 + kb + 2 * kc];
            uint32_t bh1 = *(const uint32_t*)&mh[n * QS16 + kb + 2 * kc + 8];
            uint32_t bl0 = *(const uint32_t*)&ml[n * QS16 + kb + 2 * kc];
            uint32_t bl1 = *(const uint32_t*)&ml[n * QS16 + kb + 2 * kc + 8];
            #pragma unroll
            for (int mf = 0; mf < 4; ++mf) {
                mma_f16(c[mf][ef], ah[mf][0], ah[mf][1], ah[mf][2], ah[mf][3], bh0, bh1);
                mma_f16(c[mf][ef], ah[mf][0], ah[mf][1], ah[mf][2], ah[mf][3], bl0, bl1);
                mma_f16(c[mf][ef], al[mf][0], al[mf][1], al[mf][2], al[mf][3], bh0, bh1);
            }
        }
    }

    // ---- epilogue: store fp32 sims + per-b row maxes ----
    #pragma unroll
    for (int mf = 0; mf < 4; ++mf) {
        #pragma unroll
        for (int h = 0; h < 2; ++h) {
            int row = mf * 16 + 8 * h + g;       // b index
            float rm = -1e30f;
            #pragma unroll
            for (int ef = 0; ef < 2; ++ef) {
                float lo = c[mf][ef][2 * h], hi = c[mf][ef][2 * h + 1];
                *(float2*)&g_sim[(size_t)row * SS + s0 + sw + ef * 8 + 2 * kc] =
                    make_float2(lo, hi);
                rm = fmaxf(rm, fmaxf(lo, hi));
            }
            rm = fmaxf(rm, __shfl_xor_sync(0xffffffffu, rm, 1));
            rm = fmaxf(rm, __shfl_xor_sync(0xffffffffu, rm, 2));
            if (kc == 0) wmax[wid * 64 + row] = rm;
        }
    }
    __syncthreads();
    if (tid < 64) {
        float m = wmax[tid];
        #pragma unroll
        for (int w = 1; w < 8; ++w) m = fmaxf(m, wmax[w * 64 + tid]);
        g_bmax[tid * NBLK + blockIdx.x] = m;
    }
}

// ---------------- K5s: inline threshold + fp32 stream filter ------------
// T = min over 32 group-maxes (16 bmax each): provably <= v16.
// Loads front-batched (MLP 8) before the rarely-taken filter branch.
__global__ void __launch_bounds__(256) k5s() {
    __shared__ float sT;
    int b = blockIdx.y, ch = blockIdx.x;
    int tid = threadIdx.x, lane = tid & 31;

    if (tid < 32) {
        float mx = -1e30f;
        #pragma unroll
        for (int j = 0; j < NBLK / 32; ++j)
            mx = fmaxf(mx, g_bmax[b * NBLK + lane * (NBLK / 32) + j]);
        #pragma unroll
        for (int off = 16; off; off >>= 1)
            mx = fminf(mx, __shfl_xor_sync(0xffffffffu, mx, off));
        if (lane == 0) sT = mx;
    }
    __syncthreads();

    float T = sT;
    const float4* rowv = (const float4*)(g_sim + (size_t)b * SS + (size_t)ch * CHSZ);
    int base = ch * CHSZ;

    float4 v[8];
    #pragma unroll
    for (int it = 0; it < 8; ++it) v[it] = rowv[it * 256 + tid];

    float vm = -1e30f;
    #pragma unroll
    for (int it = 0; it < 8; ++it)
        vm = fmaxf(vm, fmaxf(fmaxf(v[it].x, v[it].y), fmaxf(v[it].z, v[it].w)));

    if (vm >= T) {
        #pragma unroll
        for (int it = 0; it < 8; ++it) {
            float vals[4] = {v[it].x, v[it].y, v[it].z, v[it].w};
            int sb = base + (it * 256 + tid) * 4;
            #pragma unroll
            for (int j = 0; j < 4; ++j) {
                if (vals[j] >= T) {
                    int p = atomicAdd(&g_scnt[b], 1);
                    if (p < SCAP) {
                        g_surv_v[b * SCAP + p] = vals[j];
                        g_surv_i[b * SCAP + p] = sb + j;
                    }
                }
            }
        }
    }
}

// ---------------- K5b: final top-16 + softmax + proto gather ------------
__global__ void __launch_bounds__(128) k5b(const float* __restrict__ mem) {
    __shared__ float cv[SCAP];
    __shared__ int   ci[SCAP];
    __shared__ float selv[KTOP];
    __shared__ int   seli[KTOP];
    __shared__ float attn[KTOP];
    int b = blockIdx.x, tid = threadIdx.x, lane = tid & 31;
    int n = min(g_scnt[b], SCAP);

    for (int i = tid; i < n; i += 128) {
        cv[i] = g_surv_v[b * SCAP + i];
        ci[i] = g_surv_i[b * SCAP + i];
    }
    __syncthreads();

    if (tid < 32) {
        #pragma unroll 1
        for (int r = 0; r < KTOP; ++r) {
            float mv = -1e30f; int gi = 0x7fffffff; int mi = 0;
            for (int i = lane; i < n; i += 32) {
                float v = cv[i]; int idx = ci[i];
                if (v > mv || (v == mv && idx < gi)) { mv = v; gi = idx; mi = i; }
            }
            float bv = mv; int bgi = gi; int bmi = mi;
            #pragma unroll
            for (int off = 16; off; off >>= 1) {
                float ov  = __shfl_xor_sync(0xffffffffu, bv, off);
                int   ogi = __shfl_xor_sync(0xffffffffu, bgi, off);
                int   omi = __shfl_xor_sync(0xffffffffu, bmi, off);
                if (ov > bv || (ov == bv && ogi < bgi)) { bv = ov; bgi = ogi; bmi = omi; }
            }
            if (lane == 0) {
                selv[r] = bv; seli[r] = bgi;
                cv[bmi] = -1e30f;
            }
            __syncwarp();
        }
        if (lane == 0) {
            float mx = selv[0];
            float e[KTOP], ssum = 0.f;
            #pragma unroll
            for (int k = 0; k < KTOP; ++k) { e[k] = expf(selv[k] - mx); ssum += e[k]; }
            #pragma unroll
            for (int k = 0; k < KTOP; ++k) attn[k] = e[k] / ssum;
        }
    }
    __syncthreads();

    float acc = 0.f;
    #pragma unroll
    for (int k = 0; k < KTOP; ++k)
        acc = fmaf(attn[k], mem[(size_t)seli[k] * 128 + tid], acc);
    g_proto[b * 128 + tid] = acc;
}

// ---------------- K6: out = x + scale * proto ---------------------------
__global__ void __launch_bounds__(256) k6_add(const float* __restrict__ x,
                                              const float* __restrict__ scale_p,
                                              float* __restrict__ out) {
    __shared__ float pr[128];
    __shared__ float sc;
    int b = blockIdx.y;
    if (threadIdx.x < 128) pr[threadIdx.x] = g_proto[b * 128 + threadIdx.x];
    if (threadIdx.x == 0) sc = *scale_p;
    __syncthreads();

    float s = sc;
    const float4* xv = (const float4*)x;
    float4* ov = (float4*)out;
    size_t f0 = ((size_t)b * (NN * DD) + (size_t)blockIdx.x * 4096) >> 2;
    #pragma unroll
    for (int it = 0; it < 4; ++it) {
        size_t f = f0 + it * 256 + threadIdx.x;
        float4 v = xv[f];
        int d4 = (int)(f & 31);
        const float* p = &pr[d4 * 4];
        v.x = fmaf(s, p[0], v.x);
        v.y = fmaf(s, p[1], v.y);
        v.z = fmaf(s, p[2], v.z);
        v.w = fmaf(s, p[3], v.w);
        ov[f] = v;
    }
}

// ---------------- launch -------------------------------------------------
extern "C" void kernel_launch(void* const* d_in, const int* in_sizes, int n_in,
                              void* d_out, int out_size) {
    const float* x      = (const float*)d_in[0];
    const float* conv_w = (const float*)d_in[1];
    const float* conv_b = (const float*)d_in[2];
    const float* memory = (const float*)d_in[3];
    const float* scale  = (const float*)d_in[4];
    float* out = (float*)d_out;

    cudaFuncSetAttribute(k2_mma, cudaFuncAttributeMaxDynamicSharedMemorySize, K2_SMEM);
    cudaFuncSetAttribute(k4fh, cudaFuncAttributeMaxDynamicSharedMemorySize, K4_SMEM);

    k2_mma<<<BB * 4, 128, K2_SMEM>>>(x, conv_w, conv_b);
    k3_q<<<BB, 128>>>();
    k4fh<<<NBLK, 256, K4_SMEM>>>(memory);
    dim3 g5s(NCH, BB);
    k5s<<<g5s, 256>>>();
    k5b<<<BB, 128>>>(memory);
    dim3 g6(128, BB);
    k6_add<<<g6, 256>>>(x, scale, out);
    (void)in_sizes; (void)n_in; (void)out_size;
}